// round 15
// baseline (speedup 1.0000x reference)
#include <cuda_runtime.h>
#include <stdint.h>
#include <math.h>

// Problem constants
#define NB    16
#define HW    56
#define NPIX  3136           // 56*56
#define NBP   50176          // NB*NPIX
#define C_IN  256
#define C_MID 64
#define EPSC  1e-6f
#define BNEPS 1e-5f
#define NOUT_MAIN 12845056   // 16*256*56*56

// ---------------- scratch (__device__ globals; no allocation) ----------------
__device__ float g_cos1[C_MID*NBP];   // cosine stage 1
__device__ float g_cos2[C_MID*NBP];   // cosine stage 2
__device__ float g_cos3[NOUT_MAIN];   // cosine stage 3
__device__ float g_h   [C_MID*NBP];   // post-BN/ReLU activations (h1, then h2)
__device__ float g_ss  [NBP];         // per-pixel sumsq (stage1) / sqrt-sumsq (stage2)
__device__ float g_xn1 [NBP];         // stage-1 pixel norm sqrt(sum x^2)
__device__ float g_xn  [NBP];         // x_norm for conv2 (sqrt of 3x3 box sum)
__device__ float g_wn  [512];         // weight Frobenius norms (64 + 64 + 256)
__device__ float g_st  [768];         // BN sums/sumsq per stage
__device__ float g_acc [1];

// ---------------- f32x2 packed math ----------------
__device__ __forceinline__ void ffma2(uint64_t& d, uint64_t a, uint64_t b) {
    asm("fma.rn.f32x2 %0, %1, %2, %0;" : "+l"(d) : "l"(a), "l"(b));
}
__device__ __forceinline__ uint64_t bcast2(float w) {
    uint64_t r; asm("mov.b64 %0, {%1, %1};" : "=l"(r) : "f"(w)); return r;
}
__device__ __forceinline__ void unpack2(uint64_t v, float& lo, float& hi) {
    asm("mov.b64 {%0, %1}, %2;" : "=f"(lo), "=f"(hi) : "l"(v));
}

// ---------------- threefry2x32 (JAX-exact, partitionable mode) ----------------
__host__ __device__ __forceinline__ uint32_t rotl32(uint32_t x, int r) {
    return (x << r) | (x >> (32 - r));
}

__host__ __device__ __forceinline__ void threefry2x32(
    uint32_t k0, uint32_t k1, uint32_t c0, uint32_t c1, uint32_t& o0, uint32_t& o1)
{
    uint32_t ks0 = k0, ks1 = k1, ks2 = k0 ^ k1 ^ 0x1BD11BDAu;
    uint32_t x0 = c0 + ks0, x1 = c1 + ks1;
#define TF_R(r) { x0 += x1; x1 = rotl32(x1, r); x1 ^= x0; }
    TF_R(13) TF_R(15) TF_R(26) TF_R(6)   x0 += ks1; x1 += ks2 + 1u;
    TF_R(17) TF_R(29) TF_R(16) TF_R(24)  x0 += ks2; x1 += ks0 + 2u;
    TF_R(13) TF_R(15) TF_R(26) TF_R(6)   x0 += ks0; x1 += ks1 + 3u;
    TF_R(17) TF_R(29) TF_R(16) TF_R(24)  x0 += ks1; x1 += ks2 + 4u;
    TF_R(13) TF_R(15) TF_R(26) TF_R(6)   x0 += ks2; x1 += ks0 + 5u;
#undef TF_R
    o0 = x0; o1 = x1;
}

// Device version: rotate via widening mul so pipes split alu/fma.
__device__ __forceinline__ void threefry2x32_dev(
    uint32_t k0, uint32_t k1, uint32_t c0, uint32_t c1, uint32_t& o0, uint32_t& o1)
{
    uint32_t ks0 = k0, ks1 = k1, ks2 = k0 ^ k1 ^ 0x1BD11BDAu;
    uint32_t x0 = c0 + ks0, x1 = c1 + ks1;
#define TF_R(r) { x0 += x1; \
    uint64_t m = (uint64_t)x1 * ((uint64_t)(1u << (r))); \
    x1 = ((uint32_t)m | (uint32_t)(m >> 32)) ^ x0; }
    TF_R(13) TF_R(15) TF_R(26) TF_R(6)   x0 += ks1; x1 += ks2 + 1u;
    TF_R(17) TF_R(29) TF_R(16) TF_R(24)  x0 += ks2; x1 += ks0 + 2u;
    TF_R(13) TF_R(15) TF_R(26) TF_R(6)   x0 += ks0; x1 += ks1 + 3u;
    TF_R(17) TF_R(29) TF_R(16) TF_R(24)  x0 += ks1; x1 += ks2 + 4u;
    TF_R(13) TF_R(15) TF_R(26) TF_R(6)   x0 += ks2; x1 += ks0 + 5u;
#undef TF_R
    o0 = x0; o1 = x1;
}

// gumbel = -log(-log(u)) = C - ln2*lg2(-lg2(u)),  C = -ln(ln 2)
// No tiny-clamp: u==0 (prob 2^-23) gives -inf, which never wins an argmax
// (plane max is always finite positive), so winners are identical to JAX's.
__device__ __forceinline__ float gumbel_from_bits(uint32_t bits) {
    float u = __uint_as_float(0x3f800000u | (bits >> 9)) - 1.0f;
    float a = __log2f(u);          // <= 0
    float b = __log2f(-a);
    return fmaf(b, -0.69314718055994531f, 0.36651292058166433f);
}

__device__ __forceinline__ float gumbel_at(uint32_t k0, uint32_t k1, uint32_t e) {
    uint32_t o0, o1;
    threefry2x32_dev(k0, k1, 0u, e, o0, o1);
    return gumbel_from_bits(o0 ^ o1);
}

// ---------------- warp sampler: argmax(gumbel + 2*cos) + 11x11 mean ----------
__device__ void sample_unit(const float* __restrict__ plane,
                            uint32_t k0, uint32_t k1, int unit, float scale)
{
    int lane = threadIdx.x & 31;
    uint32_t ebase = (uint32_t)unit * (uint32_t)NPIX;
    float bv = -1e30f;
    int bi = 0;
#pragma unroll 2
    for (int p = lane; p < NPIX; p += 32) {
        float v = fmaf(plane[p], 2.0f, gumbel_at(k0, k1, ebase + (uint32_t)p));
        if (v > bv) { bv = v; bi = p; }
    }
#pragma unroll
    for (int off = 16; off; off >>= 1) {
        float ov = __shfl_xor_sync(0xffffffffu, bv, off);
        int   oi = __shfl_xor_sync(0xffffffffu, bi, off);
        if (ov > bv || (ov == bv && oi < bi)) { bv = ov; bi = oi; }
    }
    int wy = bi / HW, wx = bi - wy * HW;
    float s = 0.0f;
    for (int t = lane; t < 121; t += 32) {
        int dy = t / 11 - 5, dx = t - (t / 11) * 11 - 5;
        int yy = wy + dy, xx = wx + dx;
        if ((unsigned)yy < (unsigned)HW && (unsigned)xx < (unsigned)HW)
            s += plane[yy * HW + xx];
    }
#pragma unroll
    for (int off = 16; off; off >>= 1) s += __shfl_xor_sync(0xffffffffu, s, off);
    if (lane == 0) atomicAdd(&g_acc[0], s * scale);
}

// ---------------- combined init + weight norms ----------------
__global__ void wnorm_all_k(const float* __restrict__ w1, const float* __restrict__ w2,
                            const float* __restrict__ w3) {
    __shared__ float sm[256];
    int row = blockIdx.x;
    const float* w; int len; int r;
    if (row < 64)       { w = w1; len = 256; r = row; }
    else if (row < 128) { w = w2; len = 576; r = row - 64; }
    else                { w = w3; len = 64;  r = row - 128; }
    float s = 0.0f;
    for (int i = threadIdx.x; i < len; i += 256) {
        float v = w[(long long)r * len + i];
        s += v * v;
    }
    sm[threadIdx.x] = s; __syncthreads();
    for (int st = 128; st > 0; st >>= 1) {
        if (threadIdx.x < st) sm[threadIdx.x] += sm[threadIdx.x + st];
        __syncthreads();
    }
    if (threadIdx.x == 0) g_wn[row] = sqrtf(sm[0]);
    if (row == 0) {
        for (int i = threadIdx.x; i < 768; i += 256) g_st[i] = 0.0f;
        if (threadIdx.x == 0) g_acc[0] = 0.0f;
    }
}

// ---------------- 1x1 conv GEMM body (f32x2) + cosine + fused BN stats -------
template<int CIN, bool COMPUTE_SS>
__device__ void conv1x1_body(
    int pblk, int b, int co0,
    const float* __restrict__ X, const float* __restrict__ W,
    const float* __restrict__ wn, const float* __restrict__ xn,
    float* __restrict__ xnout, float* __restrict__ COS,
    float* __restrict__ stbase, int outC)
{
    __shared__ float sX[16][128];
    __shared__ float sW[64][17];
    __shared__ float sF[128];
    __shared__ float sWF[64];

    const int tid  = threadIdx.x;
    const int p0   = pblk * 128;
    const int px_l = tid & 127, kk2 = tid >> 7;
    const int co_g = tid >> 5,  px_g = tid & 31;

    const float* Xb = X + (long long)b * CIN * NPIX;

    if (!COMPUTE_SS) {
        if (tid < 128) {
            int pp = p0 + tid;
            float v = (pp < NPIX) ? xn[b * NPIX + pp] : 1.0f;
            sF[tid] = 1.0f / (v + EPSC);
        }
    }
    if (tid < 64) sWF[tid] = 1.0f / (wn[co0 + tid] + EPSC);

    uint64_t acc2[8][2];
#pragma unroll
    for (int i = 0; i < 8; i++) { acc2[i][0] = 0ull; acc2[i][1] = 0ull; }
    float ssacc = 0.0f;

    const int p = p0 + px_l;
    const bool pOK = p < NPIX;

    for (int kc = 0; kc < CIN; kc += 16) {
        __syncthreads();
#pragma unroll
        for (int r = 0; r < 8; r++) {
            int k = kk2 + 2 * r;
            float v = pOK ? Xb[(kc + k) * NPIX + p] : 0.0f;
            sX[k][px_l] = v;
            if (COMPUTE_SS) ssacc += v * v;
        }
        {
            int co_l = tid >> 2, ci0 = (tid & 3) * 4;
            const float* wp = W + (long long)(co0 + co_l) * CIN + kc + ci0;
#pragma unroll
            for (int r = 0; r < 4; r++) sW[co_l][ci0 + r] = wp[r];
        }
        __syncthreads();
#pragma unroll
        for (int k = 0; k < 16; k++) {
            const ulonglong2 xv = *reinterpret_cast<const ulonglong2*>(&sX[k][px_g * 4]);
#pragma unroll
            for (int i = 0; i < 8; i++) {
                uint64_t wv = bcast2(sW[co_g * 8 + i][k]);
                ffma2(acc2[i][0], wv, xv.x);
                ffma2(acc2[i][1], wv, xv.y);
            }
        }
    }

    if (COMPUTE_SS) {
        __syncthreads();
        if (kk2 == 0) sF[px_l] = ssacc;
        __syncthreads();
        if (kk2 == 1) sF[px_l] += ssacc;
        __syncthreads();
        if (tid < 128) {
            float r = sqrtf(sF[tid]);
            int pp = p0 + tid;
            if (pp < NPIX) xnout[b * NPIX + pp] = r;   // for y reconstruction
            sF[tid] = 1.0f / (r + EPSC);
        }
        __syncthreads();
    } else {
        __syncthreads();
    }

    float s1[8], s2[8];
#pragma unroll
    for (int i = 0; i < 8; i++) {
        int co_l = co_g * 8 + i;
        long long base = ((long long)(b * outC + co0 + co_l)) * NPIX;
        float wf = sWF[co_l];
        float yv[4];
        unpack2(acc2[i][0], yv[0], yv[1]);
        unpack2(acc2[i][1], yv[2], yv[3]);
        float a = 0.0f, a2 = 0.0f;
#pragma unroll
        for (int j = 0; j < 4; j++) {
            int px = px_g * 4 + j;
            int pp = p0 + px;
            if (pp < NPIX) {
                COS[base + pp] = yv[j] * wf * sF[px];
                a += yv[j]; a2 += yv[j] * yv[j];
            }
        }
        s1[i] = a; s2[i] = a2;
    }
#pragma unroll
    for (int i = 0; i < 8; i++) {
#pragma unroll
        for (int off = 16; off; off >>= 1) {
            s1[i] += __shfl_xor_sync(0xffffffffu, s1[i], off);
            s2[i] += __shfl_xor_sync(0xffffffffu, s2[i], off);
        }
    }
    if (px_g == 0) {
#pragma unroll
        for (int i = 0; i < 8; i++) {
            int c = co0 + co_g * 8 + i;
            atomicAdd(&stbase[2 * c],     s1[i]);
            atomicAdd(&stbase[2 * c + 1], s2[i]);
        }
    }
}

// Stage-1 standalone conv kernel
__global__ void __launch_bounds__(256) conv1_k(
    const float* __restrict__ X, const float* __restrict__ W,
    const float* __restrict__ wn,
    float* __restrict__ xnout, float* __restrict__ COS, float* __restrict__ stbase)
{
    conv1x1_body<C_IN, true>(blockIdx.x, blockIdx.y, 0, X, W, wn, nullptr,
                             xnout, COS, stbase, C_MID);
}

// ---------------- 3x3 conv body (64->64, pad 1), f32x2 ----------------------
// Register-blocked x reads: per ci, load 9 contiguous sX values once and
// reuse across the 3 kx taps (LDS per ci: 21 -> 9). FMA order unchanged.
// Also computes its own x_norm (3x3 box-sum of ss -> sqrt -> xnout + sF).
__device__ void conv3x3_body(
    int yy, int b,
    const float* __restrict__ Hin, const float* __restrict__ W2,
    const float* __restrict__ wn, const float* __restrict__ ss,
    float* __restrict__ xnout,
    float* __restrict__ COS, float* __restrict__ stbase)
{
    __shared__ float sX[16][60];
    __shared__ float sW[48][64];
    __shared__ float sWF[64];
    __shared__ float sF[56];
    __shared__ float sS[3][58];

    const int tid = threadIdx.x;
    const int cg = tid >> 3;   // 16 groups x 4 co
    const int pg = tid & 7;    // 8 groups x 7 px

    if (tid < 64) sWF[tid] = 1.0f / (wn[tid] + EPSC);

    // load 3 rows of ss (cols -1..56 padded) for the 3x3 box sum
    for (int f = tid; f < 174; f += 128) {
        int ry = (f >= 116) ? 2 : (f >= 58 ? 1 : 0);
        int xx = f - ry * 58;
        int r = yy - 1 + ry;
        int col = xx - 1;
        float v = 0.0f;
        if ((unsigned)r < (unsigned)HW && (unsigned)col < (unsigned)HW)
            v = ss[b * NPIX + r * HW + col];
        sS[ry][xx] = v;
    }
    __syncthreads();
    if (tid < 56) {
        float s = sS[0][tid] + sS[0][tid + 1] + sS[0][tid + 2]
                + sS[1][tid] + sS[1][tid + 1] + sS[1][tid + 2]
                + sS[2][tid] + sS[2][tid + 1] + sS[2][tid + 2];
        float r = sqrtf(s);
        xnout[b * NPIX + yy * HW + tid] = r;
        sF[tid] = 1.0f / (r + EPSC);
    }

    uint64_t acc2[2][7];
#pragma unroll
    for (int i = 0; i < 2; i++)
#pragma unroll
        for (int j = 0; j < 7; j++) acc2[i][j] = 0ull;

    const int ci_f  = tid >> 3;          // sX fill channel (0..15)
    const int x0_f  = tid & 7;           // sX fill x start
    const int co_w  = tid & 63;          // weight fill co
    const int par_w = tid >> 6;          // weight fill parity (0/1)

    for (int ky = 0; ky < 3; ky++) {
        int row = yy + ky - 1;
        bool rok = (unsigned)row < (unsigned)HW;
        for (int cc = 0; cc < 4; cc++) {
            int ci0 = cc * 16;
            __syncthreads();
            {
                const float* rowp = Hin + ((long long)(b * C_MID + ci0 + ci_f)) * NPIX
                                        + row * HW;
#pragma unroll
                for (int xx = x0_f; xx < 58; xx += 8) {
                    int col = xx - 1;
                    float v = 0.0f;
                    if (rok && (unsigned)col < (unsigned)HW) v = rowp[col];
                    sX[ci_f][xx] = v;
                }
            }
            {
                const float* wbase = W2 + (long long)co_w * 576 + ci0 * 9 + ky * 3;
                if (par_w == 0) {
#pragma unroll
                    for (int j = 0; j < 24; j++) {
                        const int rest = 2 * j;
                        const int ci = rest / 3, kx = rest - 3 * (rest / 3);
                        sW[rest][co_w] = wbase[ci * 9 + kx];
                    }
                } else {
#pragma unroll
                    for (int j = 0; j < 24; j++) {
                        const int rest = 2 * j + 1;
                        const int ci = rest / 3, kx = rest - 3 * (rest / 3);
                        sW[rest][co_w] = wbase[ci * 9 + kx];
                    }
                }
            }
            __syncthreads();
            if (!rok) continue;
#pragma unroll
            for (int ci = 0; ci < 16; ci++) {
                // load this thread's 9 x-values once (registers), reuse for all kx
                float xreg[9];
#pragma unroll
                for (int r2 = 0; r2 < 9; r2++) xreg[r2] = sX[ci][pg * 7 + r2];
#pragma unroll
                for (int kx = 0; kx < 3; kx++) {
                    const uint64_t w01 = *reinterpret_cast<const uint64_t*>(&sW[ci * 3 + kx][cg * 4]);
                    const uint64_t w23 = *reinterpret_cast<const uint64_t*>(&sW[ci * 3 + kx][cg * 4 + 2]);
#pragma unroll
                    for (int j = 0; j < 7; j++) {
                        uint64_t xv = bcast2(xreg[j + kx]);
                        ffma2(acc2[0][j], w01, xv);
                        ffma2(acc2[1][j], w23, xv);
                    }
                }
            }
        }
    }

    float accf[4][7];
#pragma unroll
    for (int j = 0; j < 7; j++) {
        unpack2(acc2[0][j], accf[0][j], accf[1][j]);
        unpack2(acc2[1][j], accf[2][j], accf[3][j]);
    }

    float s1[4], s2[4];
#pragma unroll
    for (int i = 0; i < 4; i++) {
        int co = cg * 4 + i;
        long long base = ((long long)(b * C_MID + co)) * NPIX + yy * HW;
        float wf = sWF[co];
        float a = 0.0f, a2 = 0.0f;
#pragma unroll
        for (int j = 0; j < 7; j++) {
            int x = pg * 7 + j;
            float yv = accf[i][j];
            COS[base + x] = yv * wf * sF[x];
            a += yv; a2 += yv * yv;
        }
        s1[i] = a; s2[i] = a2;
    }
#pragma unroll
    for (int i = 0; i < 4; i++) {
#pragma unroll
        for (int off = 4; off; off >>= 1) {
            s1[i] += __shfl_xor_sync(0xffffffffu, s1[i], off);
            s2[i] += __shfl_xor_sync(0xffffffffu, s2[i], off);
        }
    }
    if (pg == 0) {
#pragma unroll
        for (int i = 0; i < 4; i++) {
            int c = cg * 4 + i;
            atomicAdd(&stbase[2 * c],     s1[i]);
            atomicAdd(&stbase[2 * c + 1], s2[i]);
        }
    }
}

// ---------------- fused B: stage-1 sampler blocks + conv3x3 blocks -----------
// grid.x = 1280 + 896, block = 128 threads
__global__ void __launch_bounds__(128) fusedB_k(
    const float* __restrict__ cos1, uint32_t k0, uint32_t k1,
    const float* __restrict__ Hin, const float* __restrict__ W2,
    const float* __restrict__ wn, const float* __restrict__ ss,
    float* __restrict__ xnout,
    float* __restrict__ COS, float* __restrict__ stbase)
{
    int bid = blockIdx.x;
    if (bid < 1280) {
        int unit = bid * 4 + (threadIdx.x >> 5);     // 0..5119
        int bc = unit & 1023;                        // b*64+c
        sample_unit(cos1 + (long long)bc * NPIX, k0, k1, unit,
                    1.0f / (5120.0f * 121.0f));
        return;
    }
    int t = bid - 1280;
    conv3x3_body(t % HW, t / HW, Hin, W2, wn, ss, xnout, COS, stbase);
}

// ---------------- fused C: stage-2 sampler blocks + conv3 (1x1) blocks -------
// grid.x = 640 + 1600, block = 256 threads
__global__ void __launch_bounds__(256) fusedC_k(
    const float* __restrict__ cos2, uint32_t k0, uint32_t k1,
    const float* __restrict__ H, const float* __restrict__ W3,
    const float* __restrict__ wn, const float* __restrict__ xn,
    float* __restrict__ COS, float* __restrict__ stbase)
{
    int bid = blockIdx.x;
    if (bid < 640) {
        int unit = bid * 8 + (threadIdx.x >> 5);     // 0..5119
        int bc = unit & 1023;
        sample_unit(cos2 + (long long)bc * NPIX, k0, k1, unit,
                    1.0f / (5120.0f * 121.0f));
        return;
    }
    int t = bid - 640;                               // 0..1599
    int pblk = t % 25, b = (t / 25) & 15, z = t / 400;
    conv1x1_body<C_MID, false>(pblk, b, z * 64, H, W3, wn, xn, nullptr, COS, stbase, C_IN);
}

// ---------------- fused D: stage-3 sampler blocks + final blocks -------------
// final reconstructs y = cos * (wn+e) * (xn+e), then BN + residual + ReLU
__global__ void __launch_bounds__(256) fusedD_k(
    const float* __restrict__ cos3, uint32_t k0, uint32_t k1,
    const float4* __restrict__ C4, const float4* __restrict__ X4,
    const float* __restrict__ xn3, const float* __restrict__ wn3,
    const float* __restrict__ gam, const float* __restrict__ bet,
    const float* __restrict__ st, float4* __restrict__ out4)
{
    int bid = blockIdx.x;
    if (bid < 2560) {
        int unit = bid * 8 + (threadIdx.x >> 5);     // 0..20479
        int bc = unit & 4095;                        // b*256+c
        sample_unit(cos3 + (long long)bc * NPIX, k0, k1, unit,
                    1.0f / (20480.0f * 121.0f));
        return;
    }
    __shared__ float sc[C_IN], sh[C_IN];
    {
        int c = threadIdx.x;
        float m = st[2 * c] / (float)NBP;
        float v = st[2 * c + 1] / (float)NBP - m * m;
        float is = rsqrtf(v + BNEPS);
        sc[c] = gam[c] * is * (wn3[c] + EPSC);       // fold wn into scale
        sh[c] = bet[c] - m * gam[c] * is;
    }
    __syncthreads();
    int gid = (bid - 2560) * 256 + threadIdx.x;      // over NOUT_MAIN/4
    int plane = gid / (NPIX / 4);                    // b*256 + c
    int c = plane & 255, b = plane >> 8;
    int p4 = gid - plane * (NPIX / 4);
    const float4* xnp = (const float4*)(xn3) + b * (NPIX / 4) + p4;
    float4 cv = C4[gid], x = X4[gid], xnv = *xnp;
    float s = sc[c], h = sh[c];
    float4 o;
    o.x = fmaxf(fmaf(cv.x * (xnv.x + EPSC), s, h) + x.x, 0.0f);
    o.y = fmaxf(fmaf(cv.y * (xnv.y + EPSC), s, h) + x.y, 0.0f);
    o.z = fmaxf(fmaf(cv.z * (xnv.z + EPSC), s, h) + x.z, 0.0f);
    o.w = fmaxf(fmaf(cv.w * (xnv.w + EPSC), s, h) + x.w, 0.0f);
    out4[gid] = o;
}

// ---------------- BN apply on reconstructed y (+relu, + per-pixel sumsq) -----
template<bool SQRT_SS>
__global__ void bnapply_k(const float* __restrict__ COS,
                          const float* __restrict__ wn, const float* __restrict__ xnorm,
                          const float* __restrict__ gam, const float* __restrict__ bet,
                          const float* __restrict__ st,
                          float* __restrict__ Hout, float* __restrict__ ssout)
{
    __shared__ float sc[C_MID], sh[C_MID];
    if (threadIdx.x < C_MID) {
        int c = threadIdx.x;
        float m = st[2 * c] / (float)NBP;
        float v = st[2 * c + 1] / (float)NBP - m * m;
        float is = rsqrtf(v + BNEPS);
        sc[c] = gam[c] * is * (wn[c] + EPSC);        // fold wn into scale
        sh[c] = bet[c] - m * gam[c] * is;
    }
    __syncthreads();
    int gid = blockIdx.x * 256 + threadIdx.x;
    if (gid >= NBP) return;
    int b = gid / NPIX, p = gid - b * NPIX;
    float xnf = xnorm[gid] + EPSC;
    long long base = (long long)b * C_MID * NPIX + p;
    float ss = 0.0f;
    for (int c = 0; c < C_MID; c++) {
        float t = COS[base + c * NPIX] * xnf;
        float h = fmaxf(fmaf(t, sc[c], sh[c]), 0.0f);
        Hout[base + c * NPIX] = h;
        ss += h * h;
    }
    ssout[gid] = SQRT_SS ? sqrtf(ss) : ss;
}

__global__ void writeacc_k(float* out) { out[NOUT_MAIN] = g_acc[0]; }

// ---------------- host ----------------
static void host_keys(uint32_t* K) {
    // Partitionable (foldlike) split of key(42) = (0, 42)
    threefry2x32(0u, 42u, 0u, 0u, K[0], K[1]);   // k0
    threefry2x32(0u, 42u, 0u, 1u, K[2], K[3]);   // k1
    threefry2x32(0u, 42u, 0u, 2u, K[4], K[5]);   // k2
}

extern "C" void kernel_launch(void* const* d_in, const int* in_sizes, int n_in,
                              void* d_out, int out_size)
{
    const float* x  = (const float*)d_in[0];
    const float* w1 = (const float*)d_in[1];
    const float* w2 = (const float*)d_in[2];
    const float* w3 = (const float*)d_in[3];
    const float* g1 = (const float*)d_in[4];
    const float* b1 = (const float*)d_in[5];
    const float* g2 = (const float*)d_in[6];
    const float* b2 = (const float*)d_in[7];
    const float* g3 = (const float*)d_in[8];
    const float* b3 = (const float*)d_in[9];
    float* out = (float*)d_out;

    float *c1P, *c2P, *c3P, *hP, *ssP, *xn1P, *xnP, *wnP, *stP;
    cudaGetSymbolAddress((void**)&c1P,  g_cos1);
    cudaGetSymbolAddress((void**)&c2P,  g_cos2);
    cudaGetSymbolAddress((void**)&c3P,  g_cos3);
    cudaGetSymbolAddress((void**)&hP,   g_h);
    cudaGetSymbolAddress((void**)&ssP,  g_ss);
    cudaGetSymbolAddress((void**)&xn1P, g_xn1);
    cudaGetSymbolAddress((void**)&xnP,  g_xn);
    cudaGetSymbolAddress((void**)&wnP,  g_wn);
    cudaGetSymbolAddress((void**)&stP,  g_st);

    uint32_t K[6]; host_keys(K);

    // init + weight norms
    wnorm_all_k<<<384, 256>>>(w1, w2, w3);

    // stage 1: conv1 1x1 (256->64); writes cos1 + xn1 + BN stats
    conv1_k<<<dim3(25, NB), 256>>>(x, w1, wnP, xn1P, c1P, stP);
    bnapply_k<false><<<196, 256>>>(c1P, wnP, xn1P, g1, b1, stP, hP, ssP);

    // fused: stage-1 sampler + conv3x3 (conv3x3 computes its own x_norm from ss)
    fusedB_k<<<1280 + 896, 128>>>(c1P, K[0], K[1],
                                  hP, w2, wnP + 64, ssP, xnP, c2P, stP + 128);
    bnapply_k<true><<<196, 256>>>(c2P, wnP + 64, xnP, g2, b2, stP + 128, hP, ssP);

    // fused: stage-2 sampler + conv3 1x1 (64->256)
    fusedC_k<<<640 + 1600, 256>>>(c2P, K[2], K[3],
                                  hP, w3, wnP + 128, ssP, c3P, stP + 256);

    // fused: stage-3 sampler + final (reconstruct y + BN3 + residual + ReLU)
    fusedD_k<<<2560 + 12544, 256>>>(c3P, K[4], K[5],
                                    (const float4*)c3P, (const float4*)x,
                                    ssP, wnP + 128,
                                    g3, b3, stP + 256, (float4*)out);
    if (out_size > NOUT_MAIN) writeacc_k<<<1, 1>>>(out);
}

// round 17
// speedup vs baseline: 1.0446x; 1.0446x over previous
#include <cuda_runtime.h>
#include <stdint.h>
#include <math.h>

// Problem constants
#define NB    16
#define HW    56
#define NPIX  3136           // 56*56
#define NBP   50176          // NB*NPIX
#define C_IN  256
#define C_MID 64
#define EPSC  1e-6f
#define BNEPS 1e-5f
#define NOUT_MAIN 12845056   // 16*256*56*56

// ---------------- scratch (__device__ globals; no allocation) ----------------
__device__ float g_cos1[C_MID*NBP];   // cosine stage 1
__device__ float g_cos2[C_MID*NBP];   // cosine stage 2
__device__ float g_cos3[NOUT_MAIN];   // cosine stage 3
__device__ float g_h   [C_MID*NBP];   // post-BN/ReLU activations (h1, then h2)
__device__ float g_ss  [NBP];         // per-pixel sumsq (stage1) / sqrt-sumsq (stage2)
__device__ float g_xn1 [NBP];         // stage-1 pixel norm sqrt(sum x^2)
__device__ float g_xn  [NBP];         // x_norm for conv2 (sqrt of 3x3 box sum)
__device__ float g_wn  [512];         // weight Frobenius norms (64 + 64 + 256)
__device__ float g_st  [768];         // BN sums/sumsq per stage
__device__ float g_acc [1];

// ---------------- f32x2 packed math ----------------
__device__ __forceinline__ void ffma2(uint64_t& d, uint64_t a, uint64_t b) {
    asm("fma.rn.f32x2 %0, %1, %2, %0;" : "+l"(d) : "l"(a), "l"(b));
}
__device__ __forceinline__ uint64_t bcast2(float w) {
    uint64_t r; asm("mov.b64 %0, {%1, %1};" : "=l"(r) : "f"(w)); return r;
}
__device__ __forceinline__ void unpack2(uint64_t v, float& lo, float& hi) {
    asm("mov.b64 {%0, %1}, %2;" : "=f"(lo), "=f"(hi) : "l"(v));
}

// ---------------- threefry2x32 (JAX-exact, partitionable mode) ----------------
__host__ __device__ __forceinline__ uint32_t rotl32(uint32_t x, int r) {
    return (x << r) | (x >> (32 - r));
}

__host__ __device__ __forceinline__ void threefry2x32(
    uint32_t k0, uint32_t k1, uint32_t c0, uint32_t c1, uint32_t& o0, uint32_t& o1)
{
    uint32_t ks0 = k0, ks1 = k1, ks2 = k0 ^ k1 ^ 0x1BD11BDAu;
    uint32_t x0 = c0 + ks0, x1 = c1 + ks1;
#define TF_R(r) { x0 += x1; x1 = rotl32(x1, r); x1 ^= x0; }
    TF_R(13) TF_R(15) TF_R(26) TF_R(6)   x0 += ks1; x1 += ks2 + 1u;
    TF_R(17) TF_R(29) TF_R(16) TF_R(24)  x0 += ks2; x1 += ks0 + 2u;
    TF_R(13) TF_R(15) TF_R(26) TF_R(6)   x0 += ks0; x1 += ks1 + 3u;
    TF_R(17) TF_R(29) TF_R(16) TF_R(24)  x0 += ks1; x1 += ks2 + 4u;
    TF_R(13) TF_R(15) TF_R(26) TF_R(6)   x0 += ks2; x1 += ks0 + 5u;
#undef TF_R
    o0 = x0; o1 = x1;
}

// Device version: rotate via widening mul so pipes split alu/fma.
__device__ __forceinline__ void threefry2x32_dev(
    uint32_t k0, uint32_t k1, uint32_t c0, uint32_t c1, uint32_t& o0, uint32_t& o1)
{
    uint32_t ks0 = k0, ks1 = k1, ks2 = k0 ^ k1 ^ 0x1BD11BDAu;
    uint32_t x0 = c0 + ks0, x1 = c1 + ks1;
#define TF_R(r) { x0 += x1; \
    uint64_t m = (uint64_t)x1 * ((uint64_t)(1u << (r))); \
    x1 = ((uint32_t)m | (uint32_t)(m >> 32)) ^ x0; }
    TF_R(13) TF_R(15) TF_R(26) TF_R(6)   x0 += ks1; x1 += ks2 + 1u;
    TF_R(17) TF_R(29) TF_R(16) TF_R(24)  x0 += ks2; x1 += ks0 + 2u;
    TF_R(13) TF_R(15) TF_R(26) TF_R(6)   x0 += ks0; x1 += ks1 + 3u;
    TF_R(17) TF_R(29) TF_R(16) TF_R(24)  x0 += ks1; x1 += ks2 + 4u;
    TF_R(13) TF_R(15) TF_R(26) TF_R(6)   x0 += ks2; x1 += ks0 + 5u;
#undef TF_R
    o0 = x0; o1 = x1;
}

// gumbel = -log(-log(u)) = C - ln2*lg2(-lg2(u)),  C = -ln(ln 2)
__device__ __forceinline__ float gumbel_from_bits(uint32_t bits) {
    float u = __uint_as_float(0x3f800000u | (bits >> 9)) - 1.0f;
    float a = __log2f(u);          // <= 0
    float b = __log2f(-a);
    return fmaf(b, -0.69314718055994531f, 0.36651292058166433f);
}

__device__ __forceinline__ float gumbel_at(uint32_t k0, uint32_t k1, uint32_t e) {
    uint32_t o0, o1;
    threefry2x32_dev(k0, k1, 0u, e, o0, o1);
    return gumbel_from_bits(o0 ^ o1);
}

// ---------------- warp sampler: argmax(gumbel + 2*cos) + 11x11 mean ----------
__device__ void sample_unit(const float* __restrict__ plane,
                            uint32_t k0, uint32_t k1, int unit, float scale)
{
    int lane = threadIdx.x & 31;
    uint32_t ebase = (uint32_t)unit * (uint32_t)NPIX;
    float bv = -1e30f;
    int bi = 0;
#pragma unroll 2
    for (int p = lane; p < NPIX; p += 32) {
        float v = fmaf(plane[p], 2.0f, gumbel_at(k0, k1, ebase + (uint32_t)p));
        if (v > bv) { bv = v; bi = p; }
    }
#pragma unroll
    for (int off = 16; off; off >>= 1) {
        float ov = __shfl_xor_sync(0xffffffffu, bv, off);
        int   oi = __shfl_xor_sync(0xffffffffu, bi, off);
        if (ov > bv || (ov == bv && oi < bi)) { bv = ov; bi = oi; }
    }
    int wy = bi / HW, wx = bi - wy * HW;
    float s = 0.0f;
    for (int t = lane; t < 121; t += 32) {
        int dy = t / 11 - 5, dx = t - (t / 11) * 11 - 5;
        int yy = wy + dy, xx = wx + dx;
        if ((unsigned)yy < (unsigned)HW && (unsigned)xx < (unsigned)HW)
            s += plane[yy * HW + xx];
    }
#pragma unroll
    for (int off = 16; off; off >>= 1) s += __shfl_xor_sync(0xffffffffu, s, off);
    if (lane == 0) atomicAdd(&g_acc[0], s * scale);
}

// ---------------- combined init + weight norms ----------------
__global__ void wnorm_all_k(const float* __restrict__ w1, const float* __restrict__ w2,
                            const float* __restrict__ w3) {
    __shared__ float sm[256];
    int row = blockIdx.x;
    const float* w; int len; int r;
    if (row < 64)       { w = w1; len = 256; r = row; }
    else if (row < 128) { w = w2; len = 576; r = row - 64; }
    else                { w = w3; len = 64;  r = row - 128; }
    float s = 0.0f;
    for (int i = threadIdx.x; i < len; i += 256) {
        float v = w[(long long)r * len + i];
        s += v * v;
    }
    sm[threadIdx.x] = s; __syncthreads();
    for (int st = 128; st > 0; st >>= 1) {
        if (threadIdx.x < st) sm[threadIdx.x] += sm[threadIdx.x + st];
        __syncthreads();
    }
    if (threadIdx.x == 0) g_wn[row] = sqrtf(sm[0]);
    if (row == 0) {
        for (int i = threadIdx.x; i < 768; i += 256) g_st[i] = 0.0f;
        if (threadIdx.x == 0) g_acc[0] = 0.0f;
    }
}

// ---------------- 1x1 conv GEMM body (f32x2) + cosine + fused BN stats -------
template<int CIN, bool COMPUTE_SS>
__device__ void conv1x1_body(
    int pblk, int b, int co0,
    const float* __restrict__ X, const float* __restrict__ W,
    const float* __restrict__ wn, const float* __restrict__ xn,
    float* __restrict__ xnout, float* __restrict__ COS,
    float* __restrict__ stbase, int outC)
{
    __shared__ float sX[16][128];
    __shared__ float sW[64][17];
    __shared__ float sF[128];
    __shared__ float sWF[64];

    const int tid  = threadIdx.x;
    const int p0   = pblk * 128;
    const int px_l = tid & 127, kk2 = tid >> 7;
    const int co_g = tid >> 5,  px_g = tid & 31;

    const float* Xb = X + (long long)b * CIN * NPIX;

    if (!COMPUTE_SS) {
        if (tid < 128) {
            int pp = p0 + tid;
            float v = (pp < NPIX) ? xn[b * NPIX + pp] : 1.0f;
            sF[tid] = 1.0f / (v + EPSC);
        }
    }
    if (tid < 64) sWF[tid] = 1.0f / (wn[co0 + tid] + EPSC);

    uint64_t acc2[8][2];
#pragma unroll
    for (int i = 0; i < 8; i++) { acc2[i][0] = 0ull; acc2[i][1] = 0ull; }
    float ssacc = 0.0f;

    const int p = p0 + px_l;
    const bool pOK = p < NPIX;

    for (int kc = 0; kc < CIN; kc += 16) {
        __syncthreads();
#pragma unroll
        for (int r = 0; r < 8; r++) {
            int k = kk2 + 2 * r;
            float v = pOK ? Xb[(kc + k) * NPIX + p] : 0.0f;
            sX[k][px_l] = v;
            if (COMPUTE_SS) ssacc += v * v;
        }
        {
            int co_l = tid >> 2, ci0 = (tid & 3) * 4;
            const float* wp = W + (long long)(co0 + co_l) * CIN + kc + ci0;
#pragma unroll
            for (int r = 0; r < 4; r++) sW[co_l][ci0 + r] = wp[r];
        }
        __syncthreads();
#pragma unroll
        for (int k = 0; k < 16; k++) {
            const ulonglong2 xv = *reinterpret_cast<const ulonglong2*>(&sX[k][px_g * 4]);
#pragma unroll
            for (int i = 0; i < 8; i++) {
                uint64_t wv = bcast2(sW[co_g * 8 + i][k]);
                ffma2(acc2[i][0], wv, xv.x);
                ffma2(acc2[i][1], wv, xv.y);
            }
        }
    }

    if (COMPUTE_SS) {
        __syncthreads();
        if (kk2 == 0) sF[px_l] = ssacc;
        __syncthreads();
        if (kk2 == 1) sF[px_l] += ssacc;
        __syncthreads();
        if (tid < 128) {
            float r = sqrtf(sF[tid]);
            int pp = p0 + tid;
            if (pp < NPIX) xnout[b * NPIX + pp] = r;   // for y reconstruction
            sF[tid] = 1.0f / (r + EPSC);
        }
        __syncthreads();
    } else {
        __syncthreads();
    }

    float s1[8], s2[8];
#pragma unroll
    for (int i = 0; i < 8; i++) {
        int co_l = co_g * 8 + i;
        long long base = ((long long)(b * outC + co0 + co_l)) * NPIX;
        float wf = sWF[co_l];
        float yv[4];
        unpack2(acc2[i][0], yv[0], yv[1]);
        unpack2(acc2[i][1], yv[2], yv[3]);
        float a = 0.0f, a2 = 0.0f;
#pragma unroll
        for (int j = 0; j < 4; j++) {
            int px = px_g * 4 + j;
            int pp = p0 + px;
            if (pp < NPIX) {
                COS[base + pp] = yv[j] * wf * sF[px];
                a += yv[j]; a2 += yv[j] * yv[j];
            }
        }
        s1[i] = a; s2[i] = a2;
    }
#pragma unroll
    for (int i = 0; i < 8; i++) {
#pragma unroll
        for (int off = 16; off; off >>= 1) {
            s1[i] += __shfl_xor_sync(0xffffffffu, s1[i], off);
            s2[i] += __shfl_xor_sync(0xffffffffu, s2[i], off);
        }
    }
    if (px_g == 0) {
#pragma unroll
        for (int i = 0; i < 8; i++) {
            int c = co0 + co_g * 8 + i;
            atomicAdd(&stbase[2 * c],     s1[i]);
            atomicAdd(&stbase[2 * c + 1], s2[i]);
        }
    }
}

// Stage-1 standalone conv kernel
__global__ void __launch_bounds__(256) conv1_k(
    const float* __restrict__ X, const float* __restrict__ W,
    const float* __restrict__ wn,
    float* __restrict__ xnout, float* __restrict__ COS, float* __restrict__ stbase)
{
    conv1x1_body<C_IN, true>(blockIdx.x, blockIdx.y, 0, X, W, wn, nullptr,
                             xnout, COS, stbase, C_MID);
}

// ---------------- 3x3 conv body: 2 output rows per 256-thread block ----------
// cc-outer only: per cc, fill 4 input rows (sX) + ALL 144 weight rows (sW) in
// one sync phase -> 8 barriers/block total (was 24), Hin traffic ~2x unique.
// Also computes its own x_norm for both rows (3x3 box sum of ss).
__device__ void conv3x3_body2(
    int y0, int b,
    const float* __restrict__ Hin, const float* __restrict__ W2,
    const float* __restrict__ wn, const float* __restrict__ ss,
    float* __restrict__ xnout,
    float* __restrict__ COS, float* __restrict__ stbase)
{
    __shared__ float sX[4][16][60];    // [input row ry][ci][x(-1..58)]
    __shared__ float sW[144][64];      // [ci*9+ky*3+kx][co]
    __shared__ float sWF[64];
    __shared__ float sF[2][56];
    __shared__ float sS[4][58];

    const int tid = threadIdx.x;
    const int rr  = tid >> 7;          // output row within block (0/1)
    const int t7  = tid & 127;
    const int cg  = t7 >> 3;           // 16 groups x 4 co
    const int pg  = t7 & 7;            // 8 groups x 7 px

    if (tid < 64) sWF[tid] = 1.0f / (wn[tid] + EPSC);

    // ---- x_norm for the two output rows: load 4 rows of ss, 3x3 box sum ----
    {
        int ry = tid >> 6, xx = tid & 63;    // 4 x 64 (xx<58 used)
        if (xx < 58) {
            int r = y0 - 1 + ry, col = xx - 1;
            float v = 0.0f;
            if ((unsigned)r < (unsigned)HW && (unsigned)col < (unsigned)HW)
                v = ss[b * NPIX + r * HW + col];
            sS[ry][xx] = v;
        }
    }
    __syncthreads();
    if (tid < 128) {
        int r2 = tid >> 6, x = tid & 63;
        if (x < 56) {
            float s = sS[r2][x]     + sS[r2][x + 1]     + sS[r2][x + 2]
                    + sS[r2 + 1][x] + sS[r2 + 1][x + 1] + sS[r2 + 1][x + 2]
                    + sS[r2 + 2][x] + sS[r2 + 2][x + 1] + sS[r2 + 2][x + 2];
            float rt = sqrtf(s);
            xnout[b * NPIX + (y0 + r2) * HW + x] = rt;
            sF[r2][x] = 1.0f / (rt + EPSC);
        }
    }

    uint64_t acc2[2][7];
#pragma unroll
    for (int i = 0; i < 2; i++)
#pragma unroll
        for (int j = 0; j < 7; j++) acc2[i][j] = 0ull;

    // fill thread roles
    const int ci_f = tid >> 4;           // 16 ci
    const int sub  = tid & 15;
    const int ry_f = sub >> 2;           // 4 input rows
    const int x0_f = sub & 3;            // x start, step 4
    const int co_w = tid & 63;           // weight fill co
    const int gr_w = tid >> 6;           // weight fill row group (0..3)

    for (int cc = 0; cc < 4; cc++) {
        const int ci0 = cc * 16;
        __syncthreads();
        // sX fill: 4 rows x 16 ci x 58, strip-mined, no divisions
        {
            int row = y0 - 1 + ry_f;
            bool rok = (unsigned)row < (unsigned)HW;
            const float* rowp = Hin + ((long long)(b * C_MID + ci0 + ci_f)) * NPIX
                                    + row * HW;
#pragma unroll
            for (int xx = x0_f; xx < 58; xx += 4) {
                int col = xx - 1;
                float v = 0.0f;
                if (rok && (unsigned)col < (unsigned)HW) v = rowp[col];
                sX[ry_f][ci_f][xx] = v;
            }
        }
        // sW fill: all 144 rows, pure linear addressing
        {
            const float* wbase = W2 + (long long)co_w * 576 + ci0 * 9;
#pragma unroll
            for (int j = 0; j < 36; j++) {
                int r = gr_w + 4 * j;
                sW[r][co_w] = wbase[r];
            }
        }
        __syncthreads();
#pragma unroll
        for (int ci = 0; ci < 16; ci++) {
#pragma unroll
            for (int ky = 0; ky < 3; ky++) {
                float xreg[9];
#pragma unroll
                for (int r2 = 0; r2 < 9; r2++) xreg[r2] = sX[rr + ky][ci][pg * 7 + r2];
#pragma unroll
                for (int kx = 0; kx < 3; kx++) {
                    const int wr = ci * 9 + ky * 3 + kx;
                    const uint64_t w01 = *reinterpret_cast<const uint64_t*>(&sW[wr][cg * 4]);
                    const uint64_t w23 = *reinterpret_cast<const uint64_t*>(&sW[wr][cg * 4 + 2]);
#pragma unroll
                    for (int j = 0; j < 7; j++) {
                        uint64_t xv = bcast2(xreg[j + kx]);
                        ffma2(acc2[0][j], w01, xv);
                        ffma2(acc2[1][j], w23, xv);
                    }
                }
            }
        }
    }

    float accf[4][7];
#pragma unroll
    for (int j = 0; j < 7; j++) {
        unpack2(acc2[0][j], accf[0][j], accf[1][j]);
        unpack2(acc2[1][j], accf[2][j], accf[3][j]);
    }

    const int yy = y0 + rr;
    float s1[4], s2[4];
#pragma unroll
    for (int i = 0; i < 4; i++) {
        int co = cg * 4 + i;
        long long base = ((long long)(b * C_MID + co)) * NPIX + yy * HW;
        float wf = sWF[co];
        float a = 0.0f, a2 = 0.0f;
#pragma unroll
        for (int j = 0; j < 7; j++) {
            int x = pg * 7 + j;
            float yv = accf[i][j];
            COS[base + x] = yv * wf * sF[rr][x];
            a += yv; a2 += yv * yv;
        }
        s1[i] = a; s2[i] = a2;
    }
#pragma unroll
    for (int i = 0; i < 4; i++) {
#pragma unroll
        for (int off = 4; off; off >>= 1) {
            s1[i] += __shfl_xor_sync(0xffffffffu, s1[i], off);
            s2[i] += __shfl_xor_sync(0xffffffffu, s2[i], off);
        }
    }
    if (pg == 0) {
#pragma unroll
        for (int i = 0; i < 4; i++) {
            int c = cg * 4 + i;
            atomicAdd(&stbase[2 * c],     s1[i]);
            atomicAdd(&stbase[2 * c + 1], s2[i]);
        }
    }
}

// ---------------- fused B: stage-1 sampler blocks + conv3x3 blocks -----------
// grid.x = 640 + 448, block = 256 threads
__global__ void __launch_bounds__(256) fusedB_k(
    const float* __restrict__ cos1, uint32_t k0, uint32_t k1,
    const float* __restrict__ Hin, const float* __restrict__ W2,
    const float* __restrict__ wn, const float* __restrict__ ss,
    float* __restrict__ xnout,
    float* __restrict__ COS, float* __restrict__ stbase)
{
    int bid = blockIdx.x;
    if (bid < 640) {
        int unit = bid * 8 + (threadIdx.x >> 5);     // 0..5119
        int bc = unit & 1023;                        // b*64+c
        sample_unit(cos1 + (long long)bc * NPIX, k0, k1, unit,
                    1.0f / (5120.0f * 121.0f));
        return;
    }
    int t = bid - 640;                               // 0..447
    int yblk = t % 28, b = t / 28;
    conv3x3_body2(yblk * 2, b, Hin, W2, wn, ss, xnout, COS, stbase);
}

// ---------------- fused C: stage-2 sampler blocks + conv3 (1x1) blocks -------
// grid.x = 640 + 1600, block = 256 threads
__global__ void __launch_bounds__(256) fusedC_k(
    const float* __restrict__ cos2, uint32_t k0, uint32_t k1,
    const float* __restrict__ H, const float* __restrict__ W3,
    const float* __restrict__ wn, const float* __restrict__ xn,
    float* __restrict__ COS, float* __restrict__ stbase)
{
    int bid = blockIdx.x;
    if (bid < 640) {
        int unit = bid * 8 + (threadIdx.x >> 5);     // 0..5119
        int bc = unit & 1023;
        sample_unit(cos2 + (long long)bc * NPIX, k0, k1, unit,
                    1.0f / (5120.0f * 121.0f));
        return;
    }
    int t = bid - 640;                               // 0..1599
    int pblk = t % 25, b = (t / 25) & 15, z = t / 400;
    conv1x1_body<C_MID, false>(pblk, b, z * 64, H, W3, wn, xn, nullptr, COS, stbase, C_IN);
}

// ---------------- fused D: stage-3 sampler blocks + final blocks -------------
__global__ void __launch_bounds__(256) fusedD_k(
    const float* __restrict__ cos3, uint32_t k0, uint32_t k1,
    const float4* __restrict__ C4, const float4* __restrict__ X4,
    const float* __restrict__ xn3, const float* __restrict__ wn3,
    const float* __restrict__ gam, const float* __restrict__ bet,
    const float* __restrict__ st, float4* __restrict__ out4)
{
    int bid = blockIdx.x;
    if (bid < 2560) {
        int unit = bid * 8 + (threadIdx.x >> 5);     // 0..20479
        int bc = unit & 4095;                        // b*256+c
        sample_unit(cos3 + (long long)bc * NPIX, k0, k1, unit,
                    1.0f / (20480.0f * 121.0f));
        return;
    }
    __shared__ float sc[C_IN], sh[C_IN];
    {
        int c = threadIdx.x;
        float m = st[2 * c] / (float)NBP;
        float v = st[2 * c + 1] / (float)NBP - m * m;
        float is = rsqrtf(v + BNEPS);
        sc[c] = gam[c] * is * (wn3[c] + EPSC);       // fold wn into scale
        sh[c] = bet[c] - m * gam[c] * is;
    }
    __syncthreads();
    int gid = (bid - 2560) * 256 + threadIdx.x;      // over NOUT_MAIN/4
    int plane = gid / (NPIX / 4);                    // b*256 + c
    int c = plane & 255, b = plane >> 8;
    int p4 = gid - plane * (NPIX / 4);
    const float4* xnp = (const float4*)(xn3) + b * (NPIX / 4) + p4;
    float4 cv = C4[gid], x = X4[gid], xnv = *xnp;
    float s = sc[c], h = sh[c];
    float4 o;
    o.x = fmaxf(fmaf(cv.x * (xnv.x + EPSC), s, h) + x.x, 0.0f);
    o.y = fmaxf(fmaf(cv.y * (xnv.y + EPSC), s, h) + x.y, 0.0f);
    o.z = fmaxf(fmaf(cv.z * (xnv.z + EPSC), s, h) + x.z, 0.0f);
    o.w = fmaxf(fmaf(cv.w * (xnv.w + EPSC), s, h) + x.w, 0.0f);
    out4[gid] = o;
}

// ---------------- BN apply on reconstructed y (+relu, + per-pixel sumsq) -----
template<bool SQRT_SS>
__global__ void bnapply_k(const float* __restrict__ COS,
                          const float* __restrict__ wn, const float* __restrict__ xnorm,
                          const float* __restrict__ gam, const float* __restrict__ bet,
                          const float* __restrict__ st,
                          float* __restrict__ Hout, float* __restrict__ ssout)
{
    __shared__ float sc[C_MID], sh[C_MID];
    if (threadIdx.x < C_MID) {
        int c = threadIdx.x;
        float m = st[2 * c] / (float)NBP;
        float v = st[2 * c + 1] / (float)NBP - m * m;
        float is = rsqrtf(v + BNEPS);
        sc[c] = gam[c] * is * (wn[c] + EPSC);        // fold wn into scale
        sh[c] = bet[c] - m * gam[c] * is;
    }
    __syncthreads();
    int gid = blockIdx.x * 256 + threadIdx.x;
    if (gid >= NBP) return;
    int b = gid / NPIX, p = gid - b * NPIX;
    float xnf = xnorm[gid] + EPSC;
    long long base = (long long)b * C_MID * NPIX + p;
    float ss = 0.0f;
    for (int c = 0; c < C_MID; c++) {
        float t = COS[base + c * NPIX] * xnf;
        float h = fmaxf(fmaf(t, sc[c], sh[c]), 0.0f);
        Hout[base + c * NPIX] = h;
        ss += h * h;
    }
    ssout[gid] = SQRT_SS ? sqrtf(ss) : ss;
}

__global__ void writeacc_k(float* out) { out[NOUT_MAIN] = g_acc[0]; }

// ---------------- host ----------------
static void host_keys(uint32_t* K) {
    // Partitionable (foldlike) split of key(42) = (0, 42)
    threefry2x32(0u, 42u, 0u, 0u, K[0], K[1]);   // k0
    threefry2x32(0u, 42u, 0u, 1u, K[2], K[3]);   // k1
    threefry2x32(0u, 42u, 0u, 2u, K[4], K[5]);   // k2
}

extern "C" void kernel_launch(void* const* d_in, const int* in_sizes, int n_in,
                              void* d_out, int out_size)
{
    const float* x  = (const float*)d_in[0];
    const float* w1 = (const float*)d_in[1];
    const float* w2 = (const float*)d_in[2];
    const float* w3 = (const float*)d_in[3];
    const float* g1 = (const float*)d_in[4];
    const float* b1 = (const float*)d_in[5];
    const float* g2 = (const float*)d_in[6];
    const float* b2 = (const float*)d_in[7];
    const float* g3 = (const float*)d_in[8];
    const float* b3 = (const float*)d_in[9];
    float* out = (float*)d_out;

    float *c1P, *c2P, *c3P, *hP, *ssP, *xn1P, *xnP, *wnP, *stP;
    cudaGetSymbolAddress((void**)&c1P,  g_cos1);
    cudaGetSymbolAddress((void**)&c2P,  g_cos2);
    cudaGetSymbolAddress((void**)&c3P,  g_cos3);
    cudaGetSymbolAddress((void**)&hP,   g_h);
    cudaGetSymbolAddress((void**)&ssP,  g_ss);
    cudaGetSymbolAddress((void**)&xn1P, g_xn1);
    cudaGetSymbolAddress((void**)&xnP,  g_xn);
    cudaGetSymbolAddress((void**)&wnP,  g_wn);
    cudaGetSymbolAddress((void**)&stP,  g_st);

    uint32_t K[6]; host_keys(K);

    // init + weight norms
    wnorm_all_k<<<384, 256>>>(w1, w2, w3);

    // stage 1: conv1 1x1 (256->64); writes cos1 + xn1 + BN stats
    conv1_k<<<dim3(25, NB), 256>>>(x, w1, wnP, xn1P, c1P, stP);
    bnapply_k<false><<<196, 256>>>(c1P, wnP, xn1P, g1, b1, stP, hP, ssP);

    // fused: stage-1 sampler + conv3x3 (2 rows/block, computes own x_norm)
    fusedB_k<<<640 + 448, 256>>>(c1P, K[0], K[1],
                                 hP, w2, wnP + 64, ssP, xnP, c2P, stP + 128);
    bnapply_k<true><<<196, 256>>>(c2P, wnP + 64, xnP, g2, b2, stP + 128, hP, ssP);

    // fused: stage-2 sampler + conv3 1x1 (64->256)
    fusedC_k<<<640 + 1600, 256>>>(c2P, K[2], K[3],
                                  hP, w3, wnP + 128, ssP, c3P, stP + 256);

    // fused: stage-3 sampler + final (reconstruct y + BN3 + residual + ReLU)
    fusedD_k<<<2560 + 12544, 256>>>(c3P, K[4], K[5],
                                    (const float4*)c3P, (const float4*)x,
                                    ssP, wnP + 128,
                                    g3, b3, stP + 256, (float4*)out);
    if (out_size > NOUT_MAIN) writeacc_k<<<1, 1>>>(out);
}